// round 14
// baseline (speedup 1.0000x reference)
#include <cuda_runtime.h>
#include <cuda_bf16.h>
#include <cuda_fp16.h>
#include <math.h>

#define B_ 8
#define T_ 2048
#define H_ 64
#define M_ 32
#define S_ 20
#define E_ 3
#define IN_ 32
#define EPS_ 1e-8f
#define THR_ 30.0f  // bf16 MMA err ~<3 + half Tmax err ~<1 << 30; dropped mass ~e^-26

// Scratch (allocation-free rule: __device__ globals)
__device__ float g_mem[B_*T_*M_];
__device__ float g_Q[E_*B_*T_*M_];
__device__ float g_K[E_*B_*T_*M_];
__device__ float g_V[E_*B_*T_*M_];
__device__ __nv_bfloat16 g_Qb[E_*B_*T_*M_];
__device__ __nv_bfloat16 g_Kb[E_*B_*T_*M_];
__device__ __half g_Tmaxh[E_*B_*T_*64];   // per-(row, key-tile) approx max
__device__ float g_Rmax[E_*B_*T_];        // per-row approx max

__device__ __forceinline__ float warpSum(float v){
  #pragma unroll
  for (int o=16;o>0;o>>=1) v += __shfl_xor_sync(0xffffffffu, v, o);
  return v;
}
__device__ __forceinline__ float warpMax(float v){
  #pragma unroll
  for (int o=16;o>0;o>>=1) v = fmaxf(v, __shfl_xor_sync(0xffffffffu, v, o));
  return v;
}

__device__ __forceinline__ void mma16816(float* c, const unsigned* a,
                                         unsigned b0, unsigned b1){
  asm volatile(
    "mma.sync.aligned.m16n8k16.row.col.f32.bf16.bf16.f32 "
    "{%0,%1,%2,%3}, {%4,%5,%6,%7}, {%8,%9}, {%0,%1,%2,%3};\n"
    : "+f"(c[0]), "+f"(c[1]), "+f"(c[2]), "+f"(c[3])
    : "r"(a[0]), "r"(a[1]), "r"(a[2]), "r"(a[3]), "r"(b0), "r"(b1));
}

// ---------------------------------------------------------------------------
// Kernel 1: memories = softmax(x@IQ @ memory^T) @ memory   per (b,t)
// ---------------------------------------------------------------------------
__global__ void mem_kernel(const float* __restrict__ x,
                           const float* __restrict__ memory,
                           const float* __restrict__ iq)
{
  __shared__ float IQs[IN_*M_];
  __shared__ float MEMT[33*33];
  int tid = threadIdx.x;
  for (int i = tid; i < IN_*M_; i += 128) IQs[i] = iq[i];
  for (int i = tid; i < 33*33;  i += 128){
    int s = i / 33, m = i % 33;
    MEMT[i] = (s < S_ && m < M_) ? memory[s*M_ + m] : 0.f;
  }
  __syncthreads();

  int warp = tid >> 5, lane = tid & 31;
  int bt = blockIdx.x*4 + warp;

  // q[m], lane = m
  float xv = x[bt*IN_ + lane];
  float q = 0.f;
  #pragma unroll
  for (int i = 0; i < IN_; i++)
    q += __shfl_sync(0xffffffffu, xv, i) * IQs[i*M_ + lane];

  // scores, lane = s (lanes >= 20 masked; padded MEMT rows are zero)
  float sc = 0.f;
  #pragma unroll
  for (int m = 0; m < M_; m++)
    sc = fmaf(__shfl_sync(0xffffffffu, q, m), MEMT[lane*33 + m], sc);
  float mx = warpMax(lane < S_ ? sc : -INFINITY);
  float p  = (lane < S_) ? __expf(sc - mx) : 0.f;
  float sum = warpSum(p);

  // memories[m], lane = m
  float mval = 0.f;
  #pragma unroll
  for (int s = 0; s < S_; s++)
    mval = fmaf(__shfl_sync(0xffffffffu, p, s), MEMT[s*33 + lane], mval);
  g_mem[bt*M_ + lane] = mval / sum;
}

// ---------------------------------------------------------------------------
// Kernel 2: Q/K/V projections; also emit bf16 copies of Q,K for pass-1 MMA.
// ---------------------------------------------------------------------------
__global__ __launch_bounds__(256) void qkv_kernel(const float* __restrict__ hidden,
                           const float* __restrict__ Wq,
                           const float* __restrict__ Wk,
                           const float* __restrict__ Wv)
{
  __shared__ float Wqs[H_*M_], Wks[H_*M_], Wvs[H_*M_];
  int e = blockIdx.y;
  int tid = threadIdx.x;
  for (int i = tid; i < H_*M_; i += 256){
    Wqs[i] = Wq[e*H_*M_ + i];
    Wks[i] = Wk[e*H_*M_ + i];
    Wvs[i] = Wv[e*H_*M_ + i];
  }
  __syncthreads();

  int warp = tid >> 5, lane = tid & 31;
  int rowBase = blockIdx.x*64 + warp*8;
  #pragma unroll
  for (int rr = 0; rr < 8; rr++){
    int row = rowBase + rr;
    long gr = (long)e*B_*T_ + row;
    float h0 = hidden[gr*H_ + lane];
    float h1 = hidden[gr*H_ + 32 + lane];
    float q = 0.f, k = 0.f, v = 0.f;
    #pragma unroll
    for (int h = 0; h < 32; h++){
      float hv = __shfl_sync(0xffffffffu, h0, h);
      q += hv*Wqs[h*M_+lane]; k += hv*Wks[h*M_+lane]; v += hv*Wvs[h*M_+lane];
    }
    #pragma unroll
    for (int h = 0; h < 32; h++){
      float hv = __shfl_sync(0xffffffffu, h1, h);
      q += hv*Wqs[(h+32)*M_+lane]; k += hv*Wks[(h+32)*M_+lane]; v += hv*Wvs[(h+32)*M_+lane];
    }
    g_Q[gr*M_+lane] = q; g_K[gr*M_+lane] = k; g_V[gr*M_+lane] = v;
    g_Qb[gr*M_+lane] = __float2bfloat16(q);
    g_Kb[gr*M_+lane] = __float2bfloat16(k);
  }
}

// ---------------------------------------------------------------------------
// Kernel 3a: pass 1 (bf16 HMMA) — per-(row, 32-key-tile) max + per-row max.
// ---------------------------------------------------------------------------
__global__ __launch_bounds__(256) void attn_pass1()
{
  __shared__ char KstRaw[10240];          // 128 keys x 40 bf16 (80B rows)
  __shared__ __half Tmx[128*64];          // [row][tile] 16KB

  int tid = threadIdx.x, w = tid >> 5, lane = tid & 31;
  int gid = lane >> 2, tig = lane & 3;
  int eb = blockIdx.y;
  size_t ebT = (size_t)eb * T_;
  int qbase = blockIdx.x * 128;
  int row_lo = qbase + w*16 + gid, row_hi = row_lo + 8;

  unsigned a[8];
  {
    const __nv_bfloat16* q0 = g_Qb + (ebT + row_lo)*M_;
    const __nv_bfloat16* q1 = g_Qb + (ebT + row_hi)*M_;
    a[0]=*(const unsigned*)(q0+2*tig);    a[1]=*(const unsigned*)(q1+2*tig);
    a[2]=*(const unsigned*)(q0+2*tig+8);  a[3]=*(const unsigned*)(q1+2*tig+8);
    a[4]=*(const unsigned*)(q0+2*tig+16); a[5]=*(const unsigned*)(q1+2*tig+16);
    a[6]=*(const unsigned*)(q0+2*tig+24); a[7]=*(const unsigned*)(q1+2*tig+24);
  }

  float mlo = -INFINITY, mhi = -INFINITY;

  const unsigned* Kbg = (const unsigned*)(g_Kb + ebT*M_);
  unsigned pf[8];
  #pragma unroll
  for (int i = 0; i < 8; i++) pf[i] = Kbg[tid + i*256];

  for (int c = 0; c < 16; c++){
    __syncthreads();
    #pragma unroll
    for (int i = 0; i < 8; i++){
      int lidx = tid + i*256;
      *(unsigned*)(KstRaw + (lidx >> 4)*80 + (lidx & 15)*4) = pf[i];
    }
    __syncthreads();
    if (c < 15){
      #pragma unroll
      for (int i = 0; i < 8; i++) pf[i] = Kbg[(c+1)*2048 + tid + i*256];
    }

    #pragma unroll
    for (int t = 0; t < 4; t++){
      int kt = c*4 + t;
      float tlo = -INFINITY, thi = -INFINITY;
      #pragma unroll
      for (int nb = 0; nb < 4; nb++){
        const char* bp = KstRaw + (t*32 + nb*8 + gid)*80 + tig*4;
        unsigned b0 = *(const unsigned*)(bp);
        unsigned b1 = *(const unsigned*)(bp + 16);
        unsigned b2 = *(const unsigned*)(bp + 32);
        unsigned b3 = *(const unsigned*)(bp + 48);
        float cc[4] = {0.f, 0.f, 0.f, 0.f};
        mma16816(cc, a,   b0, b1);
        mma16816(cc, a+4, b2, b3);
        tlo = fmaxf(tlo, fmaxf(cc[0], cc[1]));
        thi = fmaxf(thi, fmaxf(cc[2], cc[3]));
      }
      tlo = fmaxf(tlo, __shfl_xor_sync(0xffffffffu, tlo, 1));
      tlo = fmaxf(tlo, __shfl_xor_sync(0xffffffffu, tlo, 2));
      thi = fmaxf(thi, __shfl_xor_sync(0xffffffffu, thi, 1));
      thi = fmaxf(thi, __shfl_xor_sync(0xffffffffu, thi, 2));
      if (tig == 0){
        Tmx[(w*16 + gid)*64 + kt]     = __float2half_rn(tlo);
        Tmx[(w*16 + gid + 8)*64 + kt] = __float2half_rn(thi);
      }
      mlo = fmaxf(mlo, tlo); mhi = fmaxf(mhi, thi);
    }
  }
  if (tig == 0){
    g_Rmax[ebT + qbase + w*16 + gid]     = mlo;
    g_Rmax[ebT + qbase + w*16 + gid + 8] = mhi;
  }
  __syncthreads();
  unsigned* dst = (unsigned*)(g_Tmaxh + (ebT + qbase)*64);
  const unsigned* src = (const unsigned*)Tmx;
  for (int i = tid; i < 4096; i += 256) dst[i] = src[i];
}

// ---------------------------------------------------------------------------
// Kernel 3b: pass 2 — float4-LDS visit engine.
//  * 4 key-tiles staged per iteration, register-prefetch double-buffered.
//  * K staged [tile][key][36] (144B rows: float4 LDS conflict-free).
//  * V staged TRANSPOSED [tile][m][36] so PV reads float4 along k.
//  * Visit: 8 bc-LDG(q float4) + 8 LDS.128(K) -> 4 FMA chains -> 1 exp;
//    p via per-warp pbuf (1 STS + 8 bc-LDS.128), PV 8 LDS.128(VT),
//    l-sum recomputed per-lane from p float4s (NO shfl chains at all).
//  * Visits assigned by row&7==w: race-free, deterministic tile order.
// smem (floats): Kbuf 4608 | Vbuf 4608 | accS 4096 | pbuf 288 | lS 128 |
//                Rm 128 | cnt 64(int) | list 64x64 u8 (1024) => 59776 B
// ---------------------------------------------------------------------------
#define P2_SMEM_ 59776

__global__ __launch_bounds__(256, 3) void attn_pass2(float* __restrict__ out)
{
  extern __shared__ char sm2[];
  float* Kbuf = (float*)sm2;                   // [4][32][36]
  float* Vbuf = Kbuf + 4608;                   // [4][32][36] transposed: [m][k]
  float* accS = Vbuf + 4608;                   // [128][32]
  float* pbuf = accS + 4096;                   // [8][36]
  float* lS   = pbuf + 288;                    // [128]
  float* Rm   = lS + 128;                      // [128]
  int*   cnt  = (int*)(Rm + 128);              // [64]
  unsigned char* list = (unsigned char*)(cnt + 64);  // [64][64]

  int tid = threadIdx.x, w = tid >> 5, lane = tid & 31;
  int eb = blockIdx.y, e = eb / B_, b = eb % B_;
  size_t ebT = (size_t)eb * T_;
  int qbase = blockIdx.x * 128;

  const float4* Kg4 = (const float4*)(g_K + ebT*M_);
  const float4* Vg4 = (const float4*)(g_V + ebT*M_);
  const float*  Qg  = g_Q + (ebT + qbase)*M_;

  // init + phase A: per-tile survivor lists
  for (int i = tid; i < 128*32; i += 256) accS[i] = 0.f;
  if (tid < 128){ Rm[tid] = g_Rmax[ebT + qbase + tid]; lS[tid] = 0.f; }
  if (tid < 64) cnt[tid] = 0;
  __syncthreads();
  {
    const __half* Tg = g_Tmaxh + (ebT + qbase)*64;
    #pragma unroll
    for (int j = 0; j < 32; j++){
      int p  = tid + j*256;               // p = row*64 + kt
      int row = p >> 6, kt = p & 63;
      if (__half2float(Tg[p]) >= Rm[row] - THR_){
        int slot = atomicAdd(&cnt[kt], 1);
        if (slot < 64) list[kt*64 + slot] = (unsigned char)row;
      }
    }
  }

  // prefetch group 0 (one group = 4 tiles = 1024 float4 of K and of V)
  float4 pk[4], pv[4];
  #pragma unroll
  for (int j = 0; j < 4; j++){
    pk[j] = __ldg(Kg4 + tid + j*256);
    pv[j] = __ldg(Vg4 + tid + j*256);
  }

  for (int g = 0; g < 16; g++){
    __syncthreads();                       // Kbuf/Vbuf free; fences phase A
    #pragma unroll
    for (int j = 0; j < 4; j++){
      int f = tid + j*256;                 // float4 idx: key = f>>3, m0 = (f&7)*4
      int key = f >> 3, m0 = (f & 7)*4;
      int t = key >> 5, kk = key & 31;
      *(float4*)(Kbuf + t*1152 + kk*36 + m0) = pk[j];
      float* vd = Vbuf + t*1152 + m0*36 + kk;    // VT[m][k]
      vd[0] = pv[j].x; vd[36] = pv[j].y; vd[72] = pv[j].z; vd[108] = pv[j].w;
    }
    __syncthreads();                       // tiles ready
    if (g < 15){
      #pragma unroll
      for (int j = 0; j < 4; j++){
        pk[j] = __ldg(Kg4 + (g+1)*1024 + tid + j*256);
        pv[j] = __ldg(Vg4 + (g+1)*1024 + tid + j*256);
      }
    }

    #pragma unroll 1
    for (int t = 0; t < 4; t++){           // ascending tile order (determinism)
      int kt = g*4 + t;
      int n = min(cnt[kt], 64);
      const float* Kt = Kbuf + t*1152;
      const float* Vt = Vbuf + t*1152;
      #pragma unroll 1
      for (int v = 0; v < n; v++){
        int row = list[kt*64 + v];
        if ((row & 7) != w) continue;      // warp-uniform
        // scores: lane = key; q broadcast via float4 LDG (L1-resident)
        const float4* q4 = (const float4*)(Qg + (size_t)row*32);
        float s0 = 0.f, s1 = 0.f, s2 = 0.f, s3 = 0.f;
        #pragma unroll
        for (int j = 0; j < 8; j++){
          float4 qv = __ldg(q4 + j);
          float4 kv = *(const float4*)(Kt + lane*36 + 4*j);
          s0 = fmaf(qv.x, kv.x, s0);
          s1 = fmaf(qv.y, kv.y, s1);
          s2 = fmaf(qv.z, kv.z, s2);
          s3 = fmaf(qv.w, kv.w, s3);
        }
        float s = (s0 + s1) + (s2 + s3);
        float p = __expf(s - Rm[row]);     // shift cancels in acc/l exactly
        pbuf[w*36 + lane] = p;
        __syncwarp();
        // PV: lane = m; p broadcast via float4 LDS, VT float4 along k
        const float4* pb4 = (const float4*)(pbuf + w*36);
        float a0 = accS[row*32 + lane], a1 = 0.f;
        float l0 = 0.f, l1 = 0.f;
        #pragma unroll
        for (int j = 0; j < 4; j++){
          float4 pp = pb4[2*j];
          float4 vv = *(const float4*)(Vt + lane*36 + 8*j);
          a0 = fmaf(pp.x, vv.x, a0); a0 = fmaf(pp.y, vv.y, a0);
          a0 = fmaf(pp.z, vv.z, a0); a0 = fmaf(pp.w, vv.w, a0);
          l0 += (pp.x + pp.y) + (pp.z + pp.w);
          float4 pq = pb4[2*j + 1];
          float4 vw = *(const float4*)(Vt + lane*36 + 8*j + 4);
          a1 = fmaf(pq.x, vw.x, a1); a1 = fmaf(pq.y, vw.y, a1);
          a1 = fmaf(pq.z, vw.z, a1); a1 = fmaf(pq.w, vw.w, a1);
          l1 += (pq.x + pq.y) + (pq.z + pq.w);
        }
        accS[row*32 + lane] = a0 + a1;
        if (lane == 0) lS[row] += l0 + l1;
        __syncwarp();                      // pbuf reused next visit
      }
    }
  }
  __syncthreads();

  // epilogue: cosine(out_row, memories[b,t]); warp owns 16 rows
  for (int r = 0; r < 16; r++){
    int row = w*16 + r, t = qbase + row;
    float o  = accS[row*32 + lane] / lS[row];
    float mv = g_mem[((size_t)b*T_ + t)*M_ + lane];
    float d  = warpSum(o*mv);
    float n1 = warpSum(o*o);
    float n2 = warpSum(mv*mv);
    if (lane == 0)
      out[((size_t)b*T_ + t)*E_ + e] =
          d / (fmaxf(sqrtf(n1), EPS_) * fmaxf(sqrtf(n2), EPS_));
  }
}

// ---------------------------------------------------------------------------
extern "C" void kernel_launch(void* const* d_in, const int* in_sizes, int n_in,
                              void* d_out, int out_size)
{
  const float* x      = (const float*)d_in[0];
  const float* hidden = (const float*)d_in[1];
  const float* memory = (const float*)d_in[2];
  const float* Wq     = (const float*)d_in[3];
  const float* Wk     = (const float*)d_in[4];
  const float* Wv     = (const float*)d_in[5];
  const float* iq     = (const float*)d_in[6];
  float* out = (float*)d_out;

  cudaFuncSetAttribute(attn_pass2, cudaFuncAttributeMaxDynamicSharedMemorySize,
                       P2_SMEM_);

  mem_kernel<<<B_*T_/4, 128>>>(x, memory, iq);
  qkv_kernel<<<dim3(B_*T_/64, E_), 256>>>(hidden, Wq, Wk, Wv);
  attn_pass1<<<dim3(T_/128, E_*B_), 256>>>();
  attn_pass2<<<dim3(T_/128, E_*B_), 256, P2_SMEM_>>>(out);
}